// round 2
// baseline (speedup 1.0000x reference)
#include <cuda_runtime.h>

// CorrelationHead fused kernel, round 2.
// out[b,o] = b_bbox[o] + sum_{c,ij,uv parity-matched} p1[b,c,ij]*p2[b,c,uv]*w[o,p,q,i,j]
//   p = (u-i)/2 + 10, q = (v-j)/2 + 10, nonzero only for u≡i, v≡j (mod 2).
//
// Grid = (512 batches, 4 channel-quarters). Each block computes a partial
// parity-class Gram over 32 channels and contracts it with the 4 weight rows.
// A tiny second kernel reduces the 4 partials + bias (fixed order, deterministic).
//
// Smem layout packs each parity class so per-thread register-tile operands are
// adjacent -> LDS.64 instead of 2x LDS.32.
//   class00 (16 vals): slot = 2*(l&7)+(l>>3)          base 0   (pairs {k,k+8})
//   class01 (12 vals): slot = 16+4*(l&3)+(l>>2)       base 16  (triples {k,k+4,k+8}, padded)
//   class10 (12 vals): slot = 32+4*(l&3)+(l>>2)       base 32
//   class11 ( 9 vals): slot = 48+4*(l%3)+(l/3)        base 48  (triples {k,k+3,k+6}, padded)

#define NB       512
#define NC       128
#define HW       49
#define FEAT     21609
#define SSTR     60      // smem row stride (58 slots used, even for float2 align)
#define CCH      32      // channels per block
#define NQ       4       // channel quarters
#define NTHREADS 128

__device__ float g_part[NB * NQ * 4];   // partial outputs [b][q][o]

__device__ __forceinline__ int perm49(int pos) {
    int i = pos / 7, j = pos - (pos / 7) * 7;
    int pi = i & 1, pj = j & 1;
    int ri = i >> 1, rj = j >> 1;
    if (!pi && !pj) { int l = ri * 4 + rj; return      2 * (l & 7) + (l >> 3); }
    if (!pi &&  pj) { int l = ri * 3 + rj; return 16 + 4 * (l & 3) + (l >> 2); }
    if ( pi && !pj) { int l = ri * 4 + rj; return 32 + 4 * (l & 3) + (l >> 2); }
    {                 int l = ri * 3 + rj; return 48 + 4 * (l % 3) + (l / 3); }
}

// contract Gram entry g at class-local (row r, col s) of class (pi,pj) with weight rows
__device__ __forceinline__ void accum_pair(float lacc[4], float g, int r, int s,
                                           int pi, int pj, int nj,
                                           const float* __restrict__ w) {
    int ri = r / nj, rj = r - (r / nj) * nj;
    int su = s / nj, sv = s - (s / nj) * nj;
    int i = 2 * ri + pi, j = 2 * rj + pj;
    int p = su - ri + 10, q = sv - rj + 10;
    int widx = ((p * 21 + q) * 7 + i) * 7 + j;
#pragma unroll
    for (int o = 0; o < 4; o++) lacc[o] += g * __ldg(&w[o * FEAT + widx]);
}

__global__ __launch_bounds__(NTHREADS) void corr_part_kernel(
    const float* __restrict__ p1, const float* __restrict__ p2,
    const float* __restrict__ w)
{
    __shared__ __align__(16) float s1[CCH * SSTR];
    __shared__ __align__(16) float s2[CCH * SSTR];
    __shared__ int permtab[HW];
    __shared__ float sred[4][4];

    const int tid = threadIdx.x;
    const int b = blockIdx.x;
    const int qtr = blockIdx.y;

    if (tid < HW) permtab[tid] = perm49(tid);
    __syncthreads();

    // ---- load 32 channels x 49 positions of both tensors into packed class layout ----
    const float4* p14 = (const float4*)(p1 + ((size_t)b * NC + qtr * CCH) * HW);
    const float4* p24 = (const float4*)(p2 + ((size_t)b * NC + qtr * CCH) * HW);
#pragma unroll
    for (int it = 0; it < 4; it++) {
        int idx4 = tid + it * NTHREADS;
        if (idx4 < CCH * HW / 4) {           // 392 float4 per tensor
            float4 v1 = p14[idx4];
            float4 v2 = p24[idx4];
            int lin = idx4 * 4;
#pragma unroll
            for (int k = 0; k < 4; k++) {
                int e = lin + k;
                int cc = e / HW;
                int pos = e - cc * HW;
                int pk = cc * SSTR + permtab[pos];
                s1[pk] = (&v1.x)[k];
                s2[pk] = (&v2.x)[k];
            }
        }
    }
    __syncthreads();

    float lacc[4] = {0.f, 0.f, 0.f, 0.f};

    if (tid < 64) {
        // ---- class00: 16x16 Gram, 8x8 threads, 2x2 tiles (rows {ty,ty+8} x cols {tx,tx+8})
        int ty = tid >> 3, tx = tid & 7;
        const float* ap = s1 + 2 * ty;
        const float* bp = s2 + 2 * tx;
        float g0 = 0.f, g1 = 0.f, g2 = 0.f, g3 = 0.f;
#pragma unroll 8
        for (int c = 0; c < CCH; c++) {
            float2 av = *(const float2*)(ap + c * SSTR);
            float2 bv = *(const float2*)(bp + c * SSTR);
            g0 += av.x * bv.x; g1 += av.x * bv.y;
            g2 += av.y * bv.x; g3 += av.y * bv.y;
        }
        accum_pair(lacc, g0, ty,     tx,     0, 0, 4, w);
        accum_pair(lacc, g1, ty,     tx + 8, 0, 0, 4, w);
        accum_pair(lacc, g2, ty + 8, tx,     0, 0, 4, w);
        accum_pair(lacc, g3, ty + 8, tx + 8, 0, 0, 4, w);
    } else if (tid < 105) {
        // ---- 3x3-tile classes: class01 (t<16), class10 (t<32), class11 (t<41)
        int t = tid - 64;
        int base, ty, tx, pi, pj, nj, rstep;
        if (t < 16)      { base = 16; ty = t >> 2;        tx = t & 3;        pi = 0; pj = 1; nj = 3; rstep = 4; }
        else if (t < 32) { int u = t - 16; base = 32; ty = u >> 2; tx = u & 3; pi = 1; pj = 0; nj = 4; rstep = 4; }
        else             { int u = t - 32; base = 48; ty = u / 3;  tx = u % 3; pi = 1; pj = 1; nj = 3; rstep = 3; }
        const float* ap = s1 + base + 4 * ty;
        const float* bp = s2 + base + 4 * tx;
        float g[9];
#pragma unroll
        for (int k = 0; k < 9; k++) g[k] = 0.f;
#pragma unroll 4
        for (int c = 0; c < CCH; c++) {
            float2 av = *(const float2*)(ap + c * SSTR);
            float  a2 = ap[c * SSTR + 2];
            float2 bv = *(const float2*)(bp + c * SSTR);
            float  b2 = bp[c * SSTR + 2];
            g[0] += av.x * bv.x; g[1] += av.x * bv.y; g[2] += av.x * b2;
            g[3] += av.y * bv.x; g[4] += av.y * bv.y; g[5] += av.y * b2;
            g[6] += a2   * bv.x; g[7] += a2   * bv.y; g[8] += a2   * b2;
        }
#pragma unroll
        for (int m = 0; m < 3; m++)
#pragma unroll
            for (int n = 0; n < 3; n++)
                accum_pair(lacc, g[m * 3 + n], ty + m * rstep, tx + n * rstep, pi, pj, nj, w);
    }

    // ---- deterministic reduction of 4 partial outputs across the block ----
#pragma unroll
    for (int off = 16; off; off >>= 1) {
#pragma unroll
        for (int o = 0; o < 4; o++)
            lacc[o] += __shfl_down_sync(0xffffffffu, lacc[o], off);
    }
    int warp = tid >> 5, lane = tid & 31;
    if (lane == 0) {
#pragma unroll
        for (int o = 0; o < 4; o++) sred[warp][o] = lacc[o];
    }
    __syncthreads();
    if (tid < 4) {
        float s = sred[0][tid] + sred[1][tid] + sred[2][tid] + sred[3][tid];
        g_part[(b * NQ + qtr) * 4 + tid] = s;
    }
}

__global__ void reduce_kernel(const float* __restrict__ bb, float* __restrict__ out)
{
    int i = blockIdx.x * blockDim.x + threadIdx.x;   // 2048 = 512*4
    if (i < NB * 4) {
        int b = i >> 2, o = i & 3;
        float s = __ldg(&bb[o]);
#pragma unroll
        for (int q = 0; q < NQ; q++) s += g_part[(b * NQ + q) * 4 + o];
        out[i] = s;
    }
}

extern "C" void kernel_launch(void* const* d_in, const int* in_sizes, int n_in,
                              void* d_out, int out_size) {
    const float* p1 = (const float*)d_in[0];   // patch1 [512,128,7,7]
    const float* p2 = (const float*)d_in[1];   // patch2 [512,128,7,7]
    const float* w  = (const float*)d_in[2];   // w_bbox [4,21609]
    const float* bb = (const float*)d_in[3];   // b_bbox [4]
    float* out = (float*)d_out;                // [512,4] float32

    dim3 grid(NB, NQ);
    corr_part_kernel<<<grid, NTHREADS>>>(p1, p2, w);
    reduce_kernel<<<8, 256>>>(bb, out);
}

// round 3
// speedup vs baseline: 1.2356x; 1.2356x over previous
#include <cuda_runtime.h>

// CorrelationHead fused kernel, round 3.
// out[b,o] = b_bbox[o] + sum_{c,(i,j),(u,v) parity-matched} p1[b,c,i,j]*p2[b,c,u,v]*w[o,p,q,i,j]
//   p = (u-i)/2 + 10, q = (v-j)/2 + 10, nonzero only for u≡i, v≡j (mod 2).
//
// One block per batch, 512 threads (16 warps = 4 channel groups x 4 parity classes).
// Parity classes over the 7x7 grid: (i%2, j%2) -> sizes 16 / 12 / 12 / 9.
// Smem slot layout per channel row (64 slots):
//   cls0 (i ev, j ev): slot =      4*rj + ri   (ri,rj in 0..3)  quads indexed by rj
//   cls1 (i ev, j od): slot = 16 + 4*rj + ri   (ri 0..3, rj 0..2)
//   cls2 (i od, j ev): slot = 32 + 4*ri + rj   (ri 0..2, rj 0..3)
//   cls3 (i od, j od): slot = 48 + 4*rj + ri   (ri,rj 0..2)
// Every Gram operand fetch is one LDS.128 (a quad). Channel-half swizzle (^16 on
// slots for channels with bit4 set) makes the two 16-lane halves bank-disjoint.

#define NB       512
#define NC       128
#define HW       49
#define FEAT     21609
#define SSTR     64
#define NTHREADS 512
#define SMEM_BYTES (2 * NC * SSTR * 4)   // 65536

__global__ __launch_bounds__(NTHREADS, 3) void corr_head_kernel(
    const float* __restrict__ p1, const float* __restrict__ p2,
    const float* __restrict__ w, const float* __restrict__ bb,
    float* __restrict__ out)
{
    extern __shared__ float sm[];
    float* s1 = sm;                 // [128][64]
    float* s2 = sm + NC * SSTR;     // [128][64]
    __shared__ int   permtab[HW];
    __shared__ float sred[16][4];

    const int tid = threadIdx.x;
    const int b = blockIdx.x;

    if (tid < HW) {
        int i = tid / 7, j = tid - (tid / 7) * 7;
        int pi = i & 1, pj = j & 1, ri = i >> 1, rj = j >> 1;
        int slot;
        if (!pi && !pj)      slot =      4 * rj + ri;
        else if (!pi)        slot = 16 + 4 * rj + ri;
        else if (!pj)        slot = 32 + 4 * ri + rj;
        else                 slot = 48 + 4 * rj + ri;
        permtab[tid] = slot;
    }
    __syncthreads();

    // ---- load both tensors (128 ch x 49 pos), scatter into swizzled class layout ----
    const float4* p14 = (const float4*)(p1 + (size_t)b * NC * HW);
    const float4* p24 = (const float4*)(p2 + (size_t)b * NC * HW);
    for (int idx4 = tid; idx4 < NC * HW / 4; idx4 += NTHREADS) {
        float4 v1 = p14[idx4];
        float4 v2 = p24[idx4];
        int lin = idx4 * 4;
#pragma unroll
        for (int k = 0; k < 4; k++) {
            int e = lin + k;
            int cc = e / HW;
            int pos = e - cc * HW;
            int pk = cc * SSTR + (permtab[pos] ^ (cc & 16));
            s1[pk] = (&v1.x)[k];
            s2[pk] = (&v2.x)[k];
        }
    }
    __syncthreads();

    // ---- per-warp Gram micro-GEMM ----
    const int warp = tid >> 5, lane = tid & 31;
    const int grp = warp >> 2;          // channel group (32 ch)
    const int cls = warp & 3;           // parity class
    const int h   = lane >> 4;          // channel half within group (16 ch)
    const int p   = lane & 15;          // tile thread

    const int nt = (cls == 0) ? 4 : 3;  // tile grid is nt x nt
    const bool active = p < nt * nt;
    const int ta = (cls == 0) ? (p >> 2) : (p / 3);
    const int tb = (cls == 0) ? (p & 3)  : (p - (p / 3) * 3);

    const int base = cls * 16;
    const int sw   = h << 4;
    const float* ap = s1 + (grp * 32 + h * 16) * SSTR + ((base + 4 * ta) ^ sw);
    const float* bp = s2 + (grp * 32 + h * 16) * SSTR + ((base + 4 * tb) ^ sw);

    float g[16];
#pragma unroll
    for (int k = 0; k < 16; k++) g[k] = 0.f;

    if (active) {
        if (cls != 3) {
#pragma unroll
            for (int c = 0; c < 16; c++) {
                float4 av = *(const float4*)(ap + c * SSTR);
                float4 bv = *(const float4*)(bp + c * SSTR);
                g[0]  += av.x * bv.x; g[1]  += av.x * bv.y; g[2]  += av.x * bv.z; g[3]  += av.x * bv.w;
                g[4]  += av.y * bv.x; g[5]  += av.y * bv.y; g[6]  += av.y * bv.z; g[7]  += av.y * bv.w;
                g[8]  += av.z * bv.x; g[9]  += av.z * bv.y; g[10] += av.z * bv.z; g[11] += av.z * bv.w;
                g[12] += av.w * bv.x; g[13] += av.w * bv.y; g[14] += av.w * bv.z; g[15] += av.w * bv.w;
            }
        } else {
#pragma unroll
            for (int c = 0; c < 16; c++) {
                float4 av = *(const float4*)(ap + c * SSTR);
                float4 bv = *(const float4*)(bp + c * SSTR);
                g[0]  += av.x * bv.x; g[1]  += av.x * bv.y; g[2]  += av.x * bv.z;
                g[4]  += av.y * bv.x; g[5]  += av.y * bv.y; g[6]  += av.y * bv.z;
                g[8]  += av.z * bv.x; g[9]  += av.z * bv.y; g[10] += av.z * bv.z;
            }
        }
    }

    // ---- merge the two channel halves (lane <- lane+16) ----
#pragma unroll
    for (int k = 0; k < 16; k++)
        g[k] += __shfl_down_sync(0xffffffffu, g[k], 16);

    // ---- contract with the 4 weight rows (h==0 lanes only) ----
    float lacc[4] = {0.f, 0.f, 0.f, 0.f};
    if (h == 0 && active) {
        const int pi = cls >> 1, pj = cls & 1;
#pragma unroll
        for (int ka = 0; ka < 4; ka++) {
#pragma unroll
            for (int kb = 0; kb < 4; kb++) {
                if (cls == 3 && (ka == 3 || kb == 3)) continue;
                float gv = g[ka * 4 + kb];
                int i, j, pp, qq;
                if (cls == 2) { i = 2 * ta + 1; j = 2 * ka;      pp = tb - ta + 10; qq = kb - ka + 10; }
                else          { i = 2 * ka + pi; j = 2 * ta + pj; pp = kb - ka + 10; qq = tb - ta + 10; }
                int widx = ((pp * 21 + qq) * 7 + i) * 7 + j;
#pragma unroll
                for (int o = 0; o < 4; o++)
                    lacc[o] += gv * __ldg(&w[o * FEAT + widx]);
            }
        }
    }

    // ---- deterministic block reduction + bias ----
#pragma unroll
    for (int off = 16; off; off >>= 1) {
#pragma unroll
        for (int o = 0; o < 4; o++)
            lacc[o] += __shfl_down_sync(0xffffffffu, lacc[o], off);
    }
    if (lane == 0) {
#pragma unroll
        for (int o = 0; o < 4; o++) sred[warp][o] = lacc[o];
    }
    __syncthreads();
    if (tid < 4) {
        float s = bb[tid];
#pragma unroll
        for (int wi = 0; wi < 16; wi++) s += sred[wi][tid];
        out[b * 4 + tid] = s;
    }
}

extern "C" void kernel_launch(void* const* d_in, const int* in_sizes, int n_in,
                              void* d_out, int out_size) {
    const float* p1 = (const float*)d_in[0];   // patch1 [512,128,7,7]
    const float* p2 = (const float*)d_in[1];   // patch2 [512,128,7,7]
    const float* w  = (const float*)d_in[2];   // w_bbox [4,21609]
    const float* bb = (const float*)d_in[3];   // b_bbox [4]
    float* out = (float*)d_out;                // [512,4] float32

    static int smem_set = 0;
    if (!smem_set) {
        cudaFuncSetAttribute(corr_head_kernel,
                             cudaFuncAttributeMaxDynamicSharedMemorySize, SMEM_BYTES);
        smem_set = 1;
    }
    corr_head_kernel<<<NB, NTHREADS, SMEM_BYTES>>>(p1, p2, w, bb, out);
}

// round 4
// speedup vs baseline: 1.5262x; 1.2352x over previous
#include <cuda_runtime.h>

// CorrelationHead fused kernel, round 4.
// out[b,o] = b_bbox[o] + sum_{c,(i,j),(u,v) parity-matched} p1[b,c,i,j]*p2[b,c,u,v]*w[o,p,q,i,j]
// One block per batch, 512 threads, 16 warps = 4 channel-groups x 4 parity classes.
// Parity-class smem slot layout (per channel row of 64 slots):
//   cls0: slot =      4*rj + ri   (ri,rj 0..3)
//   cls1: slot = 16 + 4*rj + ri   (ri 0..3, rj 0..2)
//   cls2: slot = 32 + 4*ri + rj   (ri 0..2, rj 0..3)
//   cls3: slot = 48 + 4*rj + ri   (ri,rj 0..2; element 3 of each quad zero-padded)
// Channel-half swizzle: slot ^ (channel & 16) -> dual-half LDS.128 bank-disjoint.
// Epilogue weights pre-gathered into smem wpack[(cls*16+p)*17 + pair] (float4 over o).

#define NB       512
#define NC       128
#define HW       49
#define FEAT     21609
#define SSTR     64
#define NTHREADS 512
#define WP4      (4 * 16 * 17)                     // 1088 float4
#define SMEM_FLOATS (2 * NC * SSTR + 4 * WP4)      // s1 + s2 + wpack
#define SMEM_BYTES  (SMEM_FLOATS * 4)              // 82944

__global__ __launch_bounds__(NTHREADS, 2) void corr_head_kernel(
    const float* __restrict__ p1, const float* __restrict__ p2,
    const float* __restrict__ w, const float* __restrict__ bb,
    float* __restrict__ out)
{
    extern __shared__ float sm[];
    float* s1 = sm;                      // [128][64]
    float* s2 = sm + NC * SSTR;          // [128][64]
    float* wp = sm + 2 * NC * SSTR;      // [1088 float4]
    __shared__ int   permtab[HW];
    __shared__ float sred[16][4];

    const int tid = threadIdx.x;
    const int b = blockIdx.x;

    // ---- permtab (slot layout) ----
    if (tid < HW) {
        int i = tid / 7, j = tid - (tid / 7) * 7;
        int pi = i & 1, pj = j & 1, ri = i >> 1, rj = j >> 1;
        int slot;
        if (!pi && !pj)      slot =      4 * rj + ri;
        else if (!pi)        slot = 16 + 4 * rj + ri;
        else if (!pj)        slot = 32 + 4 * ri + rj;
        else                 slot = 48 + 4 * rj + ri;
        permtab[tid] = slot;
    }

    // ---- prefetch patch data into registers (long-latency loads issued first) ----
    const float4* p14 = (const float4*)(p1 + (size_t)b * NC * HW);
    const float4* p24 = (const float4*)(p2 + (size_t)b * NC * HW);
    float4 v1[4], v2[4];
#pragma unroll
    for (int k = 0; k < 3; k++) {            // 3*512 = 1536 of 1568 float4
        v1[k] = p14[tid + k * NTHREADS];
        v2[k] = p24[tid + k * NTHREADS];
    }
    const bool tail = tid < (NC * HW / 4 - 3 * NTHREADS);   // 32
    if (tail) { v1[3] = p14[tid + 3 * NTHREADS]; v2[3] = p24[tid + 3 * NTHREADS]; }

    // ---- gather epilogue weights (2 cells/thread, independent LDGs overlap above) ----
    float wv[2][4];
    int   wcell[2];
#pragma unroll
    for (int e = 0; e < 2; e++) {
        int cell = tid + e * NTHREADS;       // 1024 cells: cls(2b) p(4b) pair(4b)
        wcell[e] = cell;
        int cls  = cell >> 8;
        int p    = (cell >> 4) & 15;
        int pair = cell & 15;
        int ka = pair >> 2, kb = pair & 3;
        int ta = (cls == 0) ? (p >> 2) : (p / 3);
        int tb = (cls == 0) ? (p & 3)  : (p - (p / 3) * 3);
        bool valid = (cls == 0) ? true
                   : (p < 9) && !(cls == 3 && (ka == 3 || kb == 3));
        int pi = cls >> 1, pj = cls & 1;
        int i, j, pp, qq;
        if (cls == 2) { i = 2 * ta + 1;  j = 2 * ka;      pp = tb - ta + 10; qq = kb - ka + 10; }
        else          { i = 2 * ka + pi; j = 2 * ta + pj; pp = kb - ka + 10; qq = tb - ta + 10; }
        int widx = ((pp * 21 + qq) * 7 + i) * 7 + j;
#pragma unroll
        for (int o = 0; o < 4; o++)
            wv[e][o] = valid ? __ldg(&w[o * FEAT + widx]) : 0.f;
    }

    // ---- zero cls3 pad slots (slot 48+4*rj+3, both tensors, all channels) ----
#pragma unroll
    for (int e = 0; e < 2; e++) {
        int task = tid + e * NTHREADS;       // 768 tasks
        if (task < 768) {
            int tens = task >= 384;
            int r = task - (tens ? 384 : 0);
            int c = r / 3, rj = r - 3 * c;
            int slot = (48 + 4 * rj + 3) ^ (c & 16);
            (tens ? s2 : s1)[c * SSTR + slot] = 0.f;
        }
    }
    __syncthreads();

    // ---- scatter patch data into class layout ----
#pragma unroll
    for (int k = 0; k < 4; k++) {
        if (k < 3 || tail) {
            int lin = (tid + k * NTHREADS) * 4;
#pragma unroll
            for (int kk = 0; kk < 4; kk++) {
                int e = lin + kk;
                int cc = e / HW;
                int pos = e - cc * HW;
                int pk = cc * SSTR + (permtab[pos] ^ (cc & 16));
                s1[pk] = (&v1[k].x)[kk];
                s2[pk] = (&v2[k].x)[kk];
            }
        }
    }
    // ---- store wpack ----
#pragma unroll
    for (int e = 0; e < 2; e++) {
        int cell = wcell[e];
        int off4 = (cell >> 4) * 17 + (cell & 15);
        ((float4*)wp)[off4] = make_float4(wv[e][0], wv[e][1], wv[e][2], wv[e][3]);
    }
    __syncthreads();

    // ---- per-warp Gram micro-GEMM: 4x4 slot tile, 4-channel operand batches ----
    const int warp = tid >> 5, lane = tid & 31;
    const int grp = warp >> 2;               // channel group (32 ch)
    const int cls = warp & 3;
    const int h   = lane >> 4;               // channel half (16 ch)
    const int p   = lane & 15;
    const bool active = (cls == 0) ? true : (p < 9);
    const int ta = (cls == 0) ? (p >> 2) : (p / 3);
    const int tb = (cls == 0) ? (p & 3)  : (p - (p / 3) * 3);

    const int sw = h << 4;
    const float* ap = s1 + (grp * 32 + h * 16) * SSTR + ((cls * 16 + 4 * ta) ^ sw);
    const float* bp = s2 + (grp * 32 + h * 16) * SSTR + ((cls * 16 + 4 * tb) ^ sw);

    float g[16];
#pragma unroll
    for (int k = 0; k < 16; k++) g[k] = 0.f;

    if (active) {
#pragma unroll
        for (int cb = 0; cb < 4; cb++) {
            float4 av[4], bv[4];
#pragma unroll
            for (int u = 0; u < 4; u++) {
                av[u] = *(const float4*)(ap + (cb * 4 + u) * SSTR);
                bv[u] = *(const float4*)(bp + (cb * 4 + u) * SSTR);
            }
#pragma unroll
            for (int u = 0; u < 4; u++) {
                g[0]  += av[u].x * bv[u].x; g[1]  += av[u].x * bv[u].y;
                g[2]  += av[u].x * bv[u].z; g[3]  += av[u].x * bv[u].w;
                g[4]  += av[u].y * bv[u].x; g[5]  += av[u].y * bv[u].y;
                g[6]  += av[u].y * bv[u].z; g[7]  += av[u].y * bv[u].w;
                g[8]  += av[u].z * bv[u].x; g[9]  += av[u].z * bv[u].y;
                g[10] += av[u].z * bv[u].z; g[11] += av[u].z * bv[u].w;
                g[12] += av[u].w * bv[u].x; g[13] += av[u].w * bv[u].y;
                g[14] += av[u].w * bv[u].z; g[15] += av[u].w * bv[u].w;
            }
        }
    }

    // ---- merge channel halves ----
#pragma unroll
    for (int k = 0; k < 16; k++)
        g[k] += __shfl_down_sync(0xffffffffu, g[k], 16);

    // ---- contract with pre-gathered weights (pure LDS, no index math) ----
    float lacc[4] = {0.f, 0.f, 0.f, 0.f};
    if (h == 0 && active) {
        const float4* wt = ((const float4*)wp) + (cls * 16 + p) * 17;
#pragma unroll
        for (int pair = 0; pair < 16; pair++) {
            float4 ww = wt[pair];
            float gv = g[pair];
            lacc[0] += gv * ww.x; lacc[1] += gv * ww.y;
            lacc[2] += gv * ww.z; lacc[3] += gv * ww.w;
        }
    }

    // ---- deterministic block reduction + bias ----
#pragma unroll
    for (int off = 16; off; off >>= 1) {
#pragma unroll
        for (int o = 0; o < 4; o++)
            lacc[o] += __shfl_down_sync(0xffffffffu, lacc[o], off);
    }
    if (lane == 0) {
#pragma unroll
        for (int o = 0; o < 4; o++) sred[warp][o] = lacc[o];
    }
    __syncthreads();
    if (tid < 4) {
        float s = bb[tid];
#pragma unroll
        for (int wi = 0; wi < 16; wi++) s += sred[wi][tid];
        out[b * 4 + tid] = s;
    }
}

extern "C" void kernel_launch(void* const* d_in, const int* in_sizes, int n_in,
                              void* d_out, int out_size) {
    const float* p1 = (const float*)d_in[0];   // patch1 [512,128,7,7]
    const float* p2 = (const float*)d_in[1];   // patch2 [512,128,7,7]
    const float* w  = (const float*)d_in[2];   // w_bbox [4,21609]
    const float* bb = (const float*)d_in[3];   // b_bbox [4]
    float* out = (float*)d_out;                // [512,4] float32

    static int smem_set = 0;
    if (!smem_set) {
        cudaFuncSetAttribute(corr_head_kernel,
                             cudaFuncAttributeMaxDynamicSharedMemorySize, SMEM_BYTES);
        smem_set = 1;
    }
    corr_head_kernel<<<NB, NTHREADS, SMEM_BYTES>>>(p1, p2, w, bb, out);
}

// round 7
// speedup vs baseline: 1.5880x; 1.0405x over previous
#include <cuda_runtime.h>

// CorrelationHead fused kernel, round 5: natural-layout Gram, zero-scatter copy.
// out[b,o] = b_bbox[o] + sum_{c,(i,j),(u,v) parity-matched} p1[b,c,i,j]*p2[b,c,u,v]*w[o,p,q,i,j]
//   p = (u-i)/2+10, q = (v-j)/2+10.
// One block per batch, 384 threads = 12 warps = 4 channel-groups x 3 warps.
//   warp wg=0: class 0 (i,j even): 16 tile-threads x 2 channel halves
//   warps wg=1,2: classes 1,2,3 (27 tile-threads) x 2 halves packed into 64 lanes
// Each tile-thread: 4x4 Gram register tile per class, reading natural s[c][49] smem
// (broadcast scalar LDS with static immediate offsets). Epilogue weights pre-gathered
// into smem wpack; invalid/dummy entries are exact zeros.

#define NB       512
#define NC       128
#define HW       49
#define FEAT     21609
#define NTHREADS 384
#define SROW     (NC * HW + 8)                 // 6280 floats per tensor (8 zero pad)
#define WP4      1088                          // 64 rows x 17 float4
#define SMEM_FLOATS (2 * SROW + 4 * WP4)       // 16912
#define SMEM_BYTES  (SMEM_FLOATS * 4)          // 67648

__global__ __launch_bounds__(NTHREADS, 3) void corr_head_kernel(
    const float* __restrict__ p1, const float* __restrict__ p2,
    const float* __restrict__ w, const float* __restrict__ bb,
    float* __restrict__ out)
{
    extern __shared__ float sm[];
    float* s1 = sm;                      // [128*49 + 8]
    float* s2 = sm + SROW;
    float* wp = sm + 2 * SROW;           // [1088 float4]
    __shared__ float sred[12][4];

    const int tid = threadIdx.x;
    const int b = blockIdx.x;

    // ---- linear copy: gmem -> natural smem layout (no index math, no conflicts) ----
    const float4* p14 = (const float4*)(p1 + (size_t)b * NC * HW);
    const float4* p24 = (const float4*)(p2 + (size_t)b * NC * HW);
    float4* s14 = (float4*)s1;
    float4* s24 = (float4*)s2;
#pragma unroll
    for (int it = 0; it < 5; it++) {
        int idx4 = tid + it * NTHREADS;
        if (idx4 < NC * HW / 4) {        // 1568
            s14[idx4] = p14[idx4];
            s24[idx4] = p24[idx4];
        }
    }
    if (tid < 8) { s1[NC * HW + tid] = 0.f; s2[NC * HW + tid] = 0.f; }

    // ---- pre-gather epilogue weights into wpack (1024 cells, zeros for invalid) ----
#pragma unroll
    for (int e = 0; e < 3; e++) {
        int cell = tid + e * NTHREADS;
        if (cell < 1024) {
            int cls = cell >> 8;
            int p   = (cell >> 4) & 15;
            int k   = cell & 15;
            int xa = k >> 2, yb = k & 3;
            int tx, ty, i, j, pp, qq;
            bool valid;
            if (cls == 0) {
                tx = p >> 2; ty = p & 3;
                i = 2 * xa; j = 2 * tx; pp = yb - xa + 10; qq = ty - tx + 10;
                valid = true;
            } else {
                tx = p / 3; ty = p - 3 * (p / 3);
                valid = (p < 9) && (cls != 3 || (xa < 3 && yb < 3));
                if (cls == 1)      { i = 2 * xa;     j = 2 * tx + 1; pp = yb - xa + 10; qq = ty - tx + 10; }
                else if (cls == 2) { i = 2 * tx + 1; j = 2 * xa;     pp = ty - tx + 10; qq = yb - xa + 10; }
                else               { i = 2 * xa + 1; j = 2 * tx + 1; pp = yb - xa + 10; qq = ty - tx + 10; }
            }
            float4 wv = make_float4(0.f, 0.f, 0.f, 0.f);
            if (valid) {
                int widx = ((pp * 21 + qq) * 7 + i) * 7 + j;
                wv.x = __ldg(&w[0 * FEAT + widx]);
                wv.y = __ldg(&w[1 * FEAT + widx]);
                wv.z = __ldg(&w[2 * FEAT + widx]);
                wv.w = __ldg(&w[3 * FEAT + widx]);
            }
            ((float4*)wp)[(cell >> 4) * 17 + k] = wv;
        }
    }
    __syncthreads();

    // ---- per-lane tile assignment ----
    const int warp = tid >> 5, lane = tid & 31;
    const int grp = warp / 3;            // channel group (32 ch)
    const int wg  = warp - 3 * grp;      // 0: cls0, 1/2: cls1-3 packed
    const int h   = lane >> 4;           // channel half (16 ch)
    const int l16 = lane & 15;

    int cls, tx, ty, pidx;
    if (wg == 0) {
        cls = 0; tx = l16 >> 2; ty = l16 & 3; pidx = l16;
    } else {
        int v = (wg - 1) * 16 + l16;     // 0..31, valid < 27
        if (v < 27) { cls = 1 + v / 9; int u = v - 9 * (v / 9); tx = u / 3; ty = u - 3 * (u / 3); }
        else        { cls = 1; tx = 3; ty = 3; }   // dummy: p=12 -> all-zero weights
        pidx = tx * 3 + ty;
    }
    int aB, bB, st;
    if (cls == 0)      { aB = 2 * tx;        bB = 2 * ty;        st = 14; }
    else if (cls == 1) { aB = 2 * tx + 1;    bB = 2 * ty + 1;    st = 14; }
    else if (cls == 2) { aB = 14 * tx + 7;   bB = 14 * ty + 7;   st = 2;  }
    else               { aB = 8 + 2 * tx;    bB = 8 + 2 * ty;    st = 14; }

    const int cb = (grp * 32 + h * 16) * HW;
    const float* a0p = s1 + cb + aB;
    const float* a1p = a0p + st;
    const float* a2p = a0p + 2 * st;
    const float* a3p = a0p + 3 * st;
    const float* b0p = s2 + cb + bB;
    const float* b1p = b0p + st;
    const float* b2p = b0p + 2 * st;
    const float* b3p = b0p + 3 * st;

    // ---- Gram over 16 channels: static-immediate LDS + 16 FMA per channel ----
    float g[16];
#pragma unroll
    for (int k = 0; k < 16; k++) g[k] = 0.f;
#pragma unroll 8
    for (int c = 0; c < 16; c++) {
        const int o = c * HW;
        float a0 = a0p[o], a1 = a1p[o], a2 = a2p[o], a3 = a3p[o];
        float b0 = b0p[o], b1 = b1p[o], b2 = b2p[o], b3 = b3p[o];
        g[0]  += a0 * b0; g[1]  += a0 * b1; g[2]  += a0 * b2; g[3]  += a0 * b3;
        g[4]  += a1 * b0; g[5]  += a1 * b1; g[6]  += a1 * b2; g[7]  += a1 * b3;
        g[8]  += a2 * b0; g[9]  += a2 * b1; g[10] += a2 * b2; g[11] += a2 * b3;
        g[12] += a3 * b0; g[13] += a3 * b1; g[14] += a3 * b2; g[15] += a3 * b3;
    }

    // ---- merge channel halves (lane <- lane+16: same tile by construction) ----
#pragma unroll
    for (int k = 0; k < 16; k++)
        g[k] += __shfl_down_sync(0xffffffffu, g[k], 16);

    // ---- contract with pre-gathered weights (zeros kill dummy/pad contributions) ----
    float lacc[4] = {0.f, 0.f, 0.f, 0.f};
    if (h == 0) {
        const float4* wr = ((const float4*)wp) + (cls * 16 + pidx) * 17;
#pragma unroll
        for (int k = 0; k < 16; k++) {
            float4 ww = wr[k];
            float gv = g[k];
            lacc[0] += gv * ww.x; lacc[1] += gv * ww.y;
            lacc[2] += gv * ww.z; lacc[3] += gv * ww.w;
        }
    }

    // ---- deterministic block reduction + bias ----
#pragma unroll
    for (int off = 16; off; off >>= 1) {
#pragma unroll
        for (int o = 0; o < 4; o++)
            lacc[o] += __shfl_down_sync(0xffffffffu, lacc[o], off);
    }
    if (lane == 0) {
#pragma unroll
        for (int o = 0; o < 4; o++) sred[warp][o] = lacc[o];
    }
    __syncthreads();
    if (tid < 4) {
        float s = bb[tid];
#pragma unroll
        for (int wi = 0; wi < 12; wi++) s += sred[wi][tid];
        out[b * 4 + tid] = s;
    }
}

extern "C" void kernel_launch(void* const* d_in, const int* in_sizes, int n_in,
                              void* d_out, int out_size) {
    const float* p1 = (const float*)d_in[0];   // patch1 [512,128,7,7]
    const float* p2 = (const float*)d_in[1];   // patch2 [512,128,7,7]
    const float* w  = (const float*)d_in[2];   // w_bbox [4,21609]
    const float* bb = (const float*)d_in[3];   // b_bbox [4]
    float* out = (float*)d_out;                // [512,4] float32

    static int smem_set = 0;
    if (!smem_set) {
        cudaFuncSetAttribute(corr_head_kernel,
                             cudaFuncAttributeMaxDynamicSharedMemorySize, SMEM_BYTES);
        smem_set = 1;
    }
    corr_head_kernel<<<NB, NTHREADS, SMEM_BYTES>>>(p1, p2, w, bb, out);
}